// round 9
// baseline (speedup 1.0000x reference)
#include <cuda_runtime.h>

#define NT 49          // tokens per window
#define DIMC 128       // channels
#define NH 4           // heads
#define HDIM 32        // head dim
#define QK_SCALE 0.17677669529663687f  // 32^-0.5
#define RPB_SZ 676     // 169 * 4
#define THREADS 256

struct SMem {
    union U {
        struct { float xs[NT * 132]; float ws[64 * 132]; } g;  // 25872 + 33792
        float attn[NH * NT * 52];                              // 40768
        float pw[64 * 132];                                    // 33792
    } u;                                                       // 59664
    union U2 {
        float qs[NH * NT * 36];   // 28224
        float os[NT * DIMC];      // 25088
    } u2;
    float ks[NH * NT * 36];
    float vs[NH * NT * 36];
    float ms[NT * NT];
    float rpb[RPB_SZ];
    int   ridx[NT * NT];
};

__device__ __forceinline__ float dot4(float4 a, float4 b) {
    return a.x * b.x + a.y * b.y + a.z * b.z + a.w * b.w;
}

__global__ __launch_bounds__(THREADS)
void wa_kernel(const float* __restrict__ x, const float* __restrict__ mask,
               const float* __restrict__ qkv_w, const float* __restrict__ qkv_b,
               const float* __restrict__ rpb_t, const float* __restrict__ proj_w,
               const float* __restrict__ proj_b, const int* __restrict__ rel_index,
               float* __restrict__ out, int nW)
{
    extern __shared__ char raw[];
    SMem& s = *reinterpret_cast<SMem*>(raw);
    const int b = blockIdx.x;
    const int tid = threadIdx.x;

    // ---------------- load x, mask, rel_index, rpb ----------------
    {
        const float4* x4 = (const float4*)(x + (size_t)b * NT * DIMC);
        float4* xs4 = (float4*)s.u.g.xs;
        for (int li = tid; li < NT * 32; li += THREADS) {
            int i = li >> 5, kq = li & 31;
            xs4[i * 33 + kq] = x4[li];
        }
        const float* mp = mask + (size_t)(b % nW) * NT * NT;
        for (int i = tid; i < NT * NT; i += THREADS) {
            s.ms[i] = mp[i];
            s.ridx[i] = rel_index[i];
        }
        for (int i = tid; i < RPB_SZ; i += THREADS) s.rpb[i] = rpb_t[i];
    }
    __syncthreads();

    const int cgrp = tid & 15;   // col group: cols = cgrp + 16*c
    const int rgrp = tid >> 4;   // row group: rows = rgrp*4 + r (rgrp < 13 active)

    // ---------------- QKV GEMM: 49x384x128 ----------------
    {
        const float4* xs4 = (const float4*)s.u.g.xs;
        float4* ws4 = (float4*)s.u.g.ws;
        for (int wt = 0; wt < 6; wt++) {
            const float4* w4 = (const float4*)(qkv_w + (size_t)wt * 64 * DIMC);
            for (int li = tid; li < 64 * 32; li += THREADS) {
                int r = li >> 5, kq = li & 31;
                ws4[r * 33 + kq] = w4[li];
            }
            __syncthreads();
            if (rgrp < 13) {
                float acc[4][4];
                #pragma unroll
                for (int r = 0; r < 4; r++)
                    #pragma unroll
                    for (int c = 0; c < 4; c++) acc[r][c] = 0.f;
                const int r0 = rgrp * 4;
                for (int kq = 0; kq < 32; kq++) {
                    float4 xa[4], wb[4];
                    #pragma unroll
                    for (int r = 0; r < 4; r++) {
                        int ii = min(r0 + r, NT - 1);
                        xa[r] = xs4[ii * 33 + kq];
                    }
                    #pragma unroll
                    for (int c = 0; c < 4; c++)
                        wb[c] = ws4[(cgrp + 16 * c) * 33 + kq];
                    #pragma unroll
                    for (int r = 0; r < 4; r++)
                        #pragma unroll
                        for (int c = 0; c < 4; c++)
                            acc[r][c] += dot4(xa[r], wb[c]);
                }
                #pragma unroll
                for (int r = 0; r < 4; r++) {
                    int i = r0 + r;
                    if (i < NT) {
                        #pragma unroll
                        for (int c = 0; c < 4; c++) {
                            int j = wt * 64 + cgrp + 16 * c;
                            float v = acc[r][c] + qkv_b[j];
                            int sel = j >> 7;          // 0=q 1=k 2=v
                            int h = (j >> 5) & 3, d = j & 31;
                            if (sel == 0) {
                                s.u2.qs[(h * NT + i) * 36 + d] = v * QK_SCALE;
                            } else if (sel == 1) {
                                s.ks[(h * NT + i) * 36 + d] = v;
                            } else {
                                s.vs[(h * NT + i) * 36 + d] = v;
                            }
                        }
                    }
                }
            }
            __syncthreads();
        }
    }

    // ---------------- attn = q @ k^T + bias + mask (2x2 microtile) ----------------
    {
        const float4* qs4 = (const float4*)s.u2.qs;
        const float4* ks4 = (const float4*)s.ks;
        for (int u = tid; u < NH * 25 * 25; u += THREADS) {
            int h = u / 625;
            int rr = u % 625;
            int it = rr / 25, jt = rr % 25;
            int i0 = it * 2, j0 = jt * 2;
            int i1 = min(i0 + 1, NT - 1), j1 = min(j0 + 1, NT - 1);
            const float4* q0 = qs4 + (h * NT + i0) * 9;
            const float4* q1 = qs4 + (h * NT + i1) * 9;
            const float4* k0 = ks4 + (h * NT + j0) * 9;
            const float4* k1 = ks4 + (h * NT + j1) * 9;
            float a00 = 0.f, a01 = 0.f, a10 = 0.f, a11 = 0.f;
            #pragma unroll
            for (int dq = 0; dq < 8; dq++) {
                float4 qa = q0[dq], qb = q1[dq], ka = k0[dq], kb = k1[dq];
                a00 += dot4(qa, ka); a01 += dot4(qa, kb);
                a10 += dot4(qb, ka); a11 += dot4(qb, kb);
            }
            // store with bias + mask
            {
                int p = i0 * NT + j0;
                s.u.attn[(h * NT + i0) * 52 + j0] = a00 + s.rpb[s.ridx[p] * NH + h] + s.ms[p];
            }
            if (j0 + 1 < NT) {
                int p = i0 * NT + j0 + 1;
                s.u.attn[(h * NT + i0) * 52 + j0 + 1] = a01 + s.rpb[s.ridx[p] * NH + h] + s.ms[p];
            }
            if (i0 + 1 < NT) {
                int p = (i0 + 1) * NT + j0;
                s.u.attn[(h * NT + i0 + 1) * 52 + j0] = a10 + s.rpb[s.ridx[p] * NH + h] + s.ms[p];
                if (j0 + 1 < NT) {
                    int p2 = (i0 + 1) * NT + j0 + 1;
                    s.u.attn[(h * NT + i0 + 1) * 52 + j0 + 1] = a11 + s.rpb[s.ridx[p2] * NH + h] + s.ms[p2];
                }
            }
        }
    }
    __syncthreads();

    // ---------------- softmax: one warp per row ----------------
    {
        const int warp = tid >> 5, lane = tid & 31;
        for (int row = warp; row < NH * NT; row += (THREADS / 32)) {
            float* a = s.u.attn + row * 52;
            float v0 = (lane < NT) ? a[lane] : -1e30f;
            float v1 = (lane + 32 < NT) ? a[lane + 32] : -1e30f;
            float m = fmaxf(v0, v1);
            #pragma unroll
            for (int o = 16; o; o >>= 1) m = fmaxf(m, __shfl_xor_sync(0xffffffffu, m, o));
            float e0 = (lane < NT) ? __expf(v0 - m) : 0.f;
            float e1 = (lane + 32 < NT) ? __expf(v1 - m) : 0.f;
            float sum = e0 + e1;
            #pragma unroll
            for (int o = 16; o; o >>= 1) sum += __shfl_xor_sync(0xffffffffu, sum, o);
            float inv = 1.f / sum;
            if (lane < NT) a[lane] = e0 * inv;
            if (lane + 32 < NT) a[lane + 32] = e1 * inv;
        }
    }
    __syncthreads();

    // ---------------- o = attn @ v (d-blocked float4) ----------------
    {
        const float4* vs4 = (const float4*)s.vs;
        float4* os4 = (float4*)s.u2.os;   // overlays qs (q dead now)
        for (int u = tid; u < NT * 32; u += THREADS) {
            int i = u >> 5, cq = u & 31;
            int h = cq >> 3, dq = cq & 7;
            const float* arow = s.u.attn + (h * NT + i) * 52;
            const float4* vb = vs4 + (h * NT) * 9 + dq;
            float4 acc = make_float4(0.f, 0.f, 0.f, 0.f);
            #pragma unroll
            for (int j = 0; j < 48; j += 4) {
                float4 a = *(const float4*)(arow + j);
                float4 w0 = vb[(j + 0) * 9];
                float4 w1 = vb[(j + 1) * 9];
                float4 w2 = vb[(j + 2) * 9];
                float4 w3 = vb[(j + 3) * 9];
                acc.x += a.x * w0.x + a.y * w1.x + a.z * w2.x + a.w * w3.x;
                acc.y += a.x * w0.y + a.y * w1.y + a.z * w2.y + a.w * w3.y;
                acc.z += a.x * w0.z + a.y * w1.z + a.z * w2.z + a.w * w3.z;
                acc.w += a.x * w0.w + a.y * w1.w + a.z * w2.w + a.w * w3.w;
            }
            {
                float a48 = arow[48];
                float4 wl = vb[48 * 9];
                acc.x += a48 * wl.x; acc.y += a48 * wl.y;
                acc.z += a48 * wl.z; acc.w += a48 * wl.w;
            }
            os4[i * 32 + cq] = acc;
        }
    }
    __syncthreads();

    // ---------------- proj: 49x128x128, pw tiles overlay attn ----------------
    {
        const float4* os4 = (const float4*)s.u2.os;
        float4* pw4 = (float4*)s.u.pw;
        for (int pt = 0; pt < 2; pt++) {
            const float4* w4 = (const float4*)(proj_w + (size_t)pt * 64 * DIMC);
            for (int li = tid; li < 64 * 32; li += THREADS) {
                int r = li >> 5, kq = li & 31;
                pw4[r * 33 + kq] = w4[li];
            }
            __syncthreads();
            if (rgrp < 13) {
                float acc[4][4];
                #pragma unroll
                for (int r = 0; r < 4; r++)
                    #pragma unroll
                    for (int c = 0; c < 4; c++) acc[r][c] = 0.f;
                const int r0 = rgrp * 4;
                for (int kq = 0; kq < 32; kq++) {
                    float4 xa[4], wb[4];
                    #pragma unroll
                    for (int r = 0; r < 4; r++) {
                        int ii = min(r0 + r, NT - 1);
                        xa[r] = os4[ii * 32 + kq];
                    }
                    #pragma unroll
                    for (int c = 0; c < 4; c++)
                        wb[c] = pw4[(cgrp + 16 * c) * 33 + kq];
                    #pragma unroll
                    for (int r = 0; r < 4; r++)
                        #pragma unroll
                        for (int c = 0; c < 4; c++)
                            acc[r][c] += dot4(xa[r], wb[c]);
                }
                #pragma unroll
                for (int r = 0; r < 4; r++) {
                    int i = r0 + r;
                    if (i < NT) {
                        #pragma unroll
                        for (int c = 0; c < 4; c++) {
                            int cc = pt * 64 + cgrp + 16 * c;
                            out[(size_t)b * NT * DIMC + i * DIMC + cc] = acc[r][c] + proj_b[cc];
                        }
                    }
                }
            }
            __syncthreads();
        }
    }
}

extern "C" void kernel_launch(void* const* d_in, const int* in_sizes, int n_in,
                              void* d_out, int out_size) {
    const float* x      = (const float*)d_in[0];
    const float* mask   = (const float*)d_in[1];
    const float* qkv_w  = (const float*)d_in[2];
    const float* qkv_b  = (const float*)d_in[3];
    const float* rpb_t  = (const float*)d_in[4];
    const float* proj_w = (const float*)d_in[5];
    const float* proj_b = (const float*)d_in[6];
    const int*   rel    = (const int*)d_in[7];
    float* out = (float*)d_out;

    int B  = in_sizes[0] / (NT * DIMC);     // 4096
    int nW = in_sizes[1] / (NT * NT);       // 64

    size_t smem = sizeof(SMem);
    cudaFuncSetAttribute(wa_kernel, cudaFuncAttributeMaxDynamicSharedMemorySize, (int)smem);
    wa_kernel<<<B, THREADS, smem>>>(x, mask, qkv_w, qkv_b, rpb_t, proj_w, proj_b, rel, out, nW);
}

// round 12
// speedup vs baseline: 1.4184x; 1.4184x over previous
#include <cuda_runtime.h>
#include <cstdint>

#define NT 49          // tokens per window
#define DIMC 128       // channels
#define NH 4           // heads
#define HDIM 32        // head dim
#define QK_SCALE 0.17677669529663687f  // 32^-0.5
#define RPB_SZ 676     // 169 * 4
#define THREADS 256
#define MPAD 64        // M padded to 64 for m16 tiles

struct SMem {
    union U {
        struct { float xs[MPAD * 132]; float ws[64 * 132]; } g;  // 33792 + 33792 B
        float attn[NH * NT * 52];                                // 40768 B
        float pw[64 * 132];                                      // 33792 B
    } u;                                                         // 67584 B
    union U2 {
        float qs[NH * NT * 36];   // 28224 B
        float os[MPAD * 132];     // 33792 B (stride 132 for conflict-free frags)
    } u2;
    float ks[NH * NT * 36];
    float vs[NH * NT * 36];
    float ms[NT * NT];
    float rpb[RPB_SZ];
    float bq[3 * DIMC];   // qkv bias
    float bp[DIMC];       // proj bias
    int   ridx[NT * NT];
};

__device__ __forceinline__ float dot4(float4 a, float4 b) {
    return a.x * b.x + a.y * b.y + a.z * b.z + a.w * b.w;
}

__device__ __forceinline__ float to_tf32(float v) {
    uint32_t u;
    asm("cvt.rna.tf32.f32 %0, %1;" : "=r"(u) : "f"(v));
    return __uint_as_float(u);
}

__device__ __forceinline__ void mma_tf32(float* c, const uint32_t* a, const uint32_t* b) {
    asm volatile(
        "mma.sync.aligned.m16n8k8.row.col.f32.tf32.tf32.f32 "
        "{%0,%1,%2,%3}, {%4,%5,%6,%7}, {%8,%9}, {%0,%1,%2,%3};\n"
        : "+f"(c[0]), "+f"(c[1]), "+f"(c[2]), "+f"(c[3])
        : "r"(a[0]), "r"(a[1]), "r"(a[2]), "r"(a[3]), "r"(b[0]), "r"(b[1]));
}

__device__ __forceinline__ void store_qkv(SMem& s, int i, int j, float v) {
    if (i >= NT) return;
    int sel = j >> 7, h = (j >> 5) & 3, d = j & 31;
    if (sel == 0)      s.u2.qs[(h * NT + i) * 36 + d] = v * QK_SCALE;
    else if (sel == 1) s.ks[(h * NT + i) * 36 + d] = v;
    else               s.vs[(h * NT + i) * 36 + d] = v;
}

__global__ __launch_bounds__(THREADS)
void wa_kernel(const float* __restrict__ x, const float* __restrict__ mask,
               const float* __restrict__ qkv_w, const float* __restrict__ qkv_b,
               const float* __restrict__ rpb_t, const float* __restrict__ proj_w,
               const float* __restrict__ proj_b, const int* __restrict__ rel_index,
               float* __restrict__ out, int nW)
{
    extern __shared__ char raw[];
    SMem& s = *reinterpret_cast<SMem*>(raw);
    const int b = blockIdx.x;
    const int tid = threadIdx.x;
    const int lane = tid & 31, warp = tid >> 5;
    const int g = lane >> 2, t = lane & 3;       // mma fragment coords
    const int mt2 = warp >> 2, nq = warp & 3;    // warp tile: rows mt2*32, cols nq*16

    // ---------------- load x (tf32, zero-padded to 64 rows), mask, ridx, rpb, biases ----
    {
        const float4* x4 = (const float4*)(x + (size_t)b * NT * DIMC);
        float4* xs4 = (float4*)s.u.g.xs;
        for (int li = tid; li < MPAD * 32; li += THREADS) {
            int i = li >> 5, kq = li & 31;
            float4 v = (i < NT) ? x4[i * 32 + kq] : make_float4(0.f, 0.f, 0.f, 0.f);
            xs4[i * 33 + kq] = make_float4(to_tf32(v.x), to_tf32(v.y), to_tf32(v.z), to_tf32(v.w));
        }
        const float* mp = mask + (size_t)(b % nW) * NT * NT;
        for (int i = tid; i < NT * NT; i += THREADS) {
            s.ms[i] = mp[i];
            s.ridx[i] = rel_index[i];
        }
        for (int i = tid; i < RPB_SZ; i += THREADS) s.rpb[i] = rpb_t[i];
        for (int i = tid; i < 3 * DIMC; i += THREADS) s.bq[i] = qkv_b[i];
        for (int i = tid; i < DIMC; i += THREADS) s.bp[i] = proj_b[i];
    }
    __syncthreads();

    // ---------------- QKV GEMM via tf32 mma: (64)x384x128, W in 6 chunks of 64 cols ----
    {
        const float* xsf = s.u.g.xs;
        const float* wsf = s.u.g.ws;
        for (int wt = 0; wt < 6; wt++) {
            const float4* w4 = (const float4*)(qkv_w + (size_t)wt * 64 * DIMC);
            float4* ws4 = (float4*)s.u.g.ws;
            for (int li = tid; li < 64 * 32; li += THREADS) {
                int r = li >> 5, kq = li & 31;
                float4 v = w4[li];
                ws4[r * 33 + kq] = make_float4(to_tf32(v.x), to_tf32(v.y), to_tf32(v.z), to_tf32(v.w));
            }
            __syncthreads();

            float acc[2][2][4] = {};
            #pragma unroll
            for (int ks = 0; ks < 16; ks++) {
                const int k0 = ks * 8;
                uint32_t A[2][4], B[2][2];
                #pragma unroll
                for (int mt = 0; mt < 2; mt++) {
                    const float* p = xsf + (mt2 * 32 + mt * 16 + g) * 132 + k0 + t;
                    A[mt][0] = __float_as_uint(p[0]);
                    A[mt][1] = __float_as_uint(p[8 * 132]);
                    A[mt][2] = __float_as_uint(p[4]);
                    A[mt][3] = __float_as_uint(p[8 * 132 + 4]);
                }
                #pragma unroll
                for (int nt = 0; nt < 2; nt++) {
                    const float* p = wsf + (nq * 16 + nt * 8 + g) * 132 + k0 + t;
                    B[nt][0] = __float_as_uint(p[0]);
                    B[nt][1] = __float_as_uint(p[4]);
                }
                #pragma unroll
                for (int mt = 0; mt < 2; mt++)
                    #pragma unroll
                    for (int nt = 0; nt < 2; nt++)
                        mma_tf32(acc[mt][nt], A[mt], B[nt]);
            }

            #pragma unroll
            for (int mt = 0; mt < 2; mt++) {
                const int r0 = mt2 * 32 + mt * 16 + g;
                #pragma unroll
                for (int nt = 0; nt < 2; nt++) {
                    const int j0 = wt * 64 + nq * 16 + nt * 8 + t * 2;
                    float bj0 = s.bq[j0], bj1 = s.bq[j0 + 1];
                    store_qkv(s, r0,     j0,     acc[mt][nt][0] + bj0);
                    store_qkv(s, r0,     j0 + 1, acc[mt][nt][1] + bj1);
                    store_qkv(s, r0 + 8, j0,     acc[mt][nt][2] + bj0);
                    store_qkv(s, r0 + 8, j0 + 1, acc[mt][nt][3] + bj1);
                }
            }
            __syncthreads();
        }
    }

    // ---------------- attn = q @ k^T + bias + mask (fp32 SIMT, 2x2 microtile) --------
    {
        const float4* qs4 = (const float4*)s.u2.qs;
        const float4* ks4 = (const float4*)s.ks;
        for (int u = tid; u < NH * 25 * 25; u += THREADS) {
            int h = u / 625;
            int rr = u % 625;
            int it = rr / 25, jt = rr % 25;
            int i0 = it * 2, j0 = jt * 2;
            int i1 = min(i0 + 1, NT - 1), j1 = min(j0 + 1, NT - 1);
            const float4* q0 = qs4 + (h * NT + i0) * 9;
            const float4* q1 = qs4 + (h * NT + i1) * 9;
            const float4* k0 = ks4 + (h * NT + j0) * 9;
            const float4* k1 = ks4 + (h * NT + j1) * 9;
            float a00 = 0.f, a01 = 0.f, a10 = 0.f, a11 = 0.f;
            #pragma unroll
            for (int dq = 0; dq < 8; dq++) {
                float4 qa = q0[dq], qb = q1[dq], ka = k0[dq], kb = k1[dq];
                a00 += dot4(qa, ka); a01 += dot4(qa, kb);
                a10 += dot4(qb, ka); a11 += dot4(qb, kb);
            }
            {
                int p = i0 * NT + j0;
                s.u.attn[(h * NT + i0) * 52 + j0] = a00 + s.rpb[s.ridx[p] * NH + h] + s.ms[p];
            }
            if (j0 + 1 < NT) {
                int p = i0 * NT + j0 + 1;
                s.u.attn[(h * NT + i0) * 52 + j0 + 1] = a01 + s.rpb[s.ridx[p] * NH + h] + s.ms[p];
            }
            if (i0 + 1 < NT) {
                int p = (i0 + 1) * NT + j0;
                s.u.attn[(h * NT + i0 + 1) * 52 + j0] = a10 + s.rpb[s.ridx[p] * NH + h] + s.ms[p];
                if (j0 + 1 < NT) {
                    int p2 = (i0 + 1) * NT + j0 + 1;
                    s.u.attn[(h * NT + i0 + 1) * 52 + j0 + 1] = a11 + s.rpb[s.ridx[p2] * NH + h] + s.ms[p2];
                }
            }
        }
    }
    __syncthreads();

    // ---------------- softmax: one warp per row ----------------
    {
        for (int row = warp; row < NH * NT; row += (THREADS / 32)) {
            float* a = s.u.attn + row * 52;
            float v0 = (lane < NT) ? a[lane] : -1e30f;
            float v1 = (lane + 32 < NT) ? a[lane + 32] : -1e30f;
            float m = fmaxf(v0, v1);
            #pragma unroll
            for (int o = 16; o; o >>= 1) m = fmaxf(m, __shfl_xor_sync(0xffffffffu, m, o));
            float e0 = (lane < NT) ? __expf(v0 - m) : 0.f;
            float e1 = (lane + 32 < NT) ? __expf(v1 - m) : 0.f;
            float sum = e0 + e1;
            #pragma unroll
            for (int o = 16; o; o >>= 1) sum += __shfl_xor_sync(0xffffffffu, sum, o);
            float inv = 1.f / sum;
            if (lane < NT) a[lane] = e0 * inv;
            if (lane + 32 < NT) a[lane + 32] = e1 * inv;
        }
    }
    __syncthreads();

    // ---------------- o = attn @ v (fp32 SIMT), store tf32-rounded, pad rows zeroed ----
    {
        const float4* vs4 = (const float4*)s.vs;
        float4* os4 = (float4*)s.u2.os;   // overlays qs (q dead now); stride 33 float4
        for (int u = tid; u < MPAD * 32; u += THREADS) {
            int i = u >> 5, cq = u & 31;
            if (i >= NT) {
                os4[i * 33 + cq] = make_float4(0.f, 0.f, 0.f, 0.f);
                continue;
            }
            int h = cq >> 3, dq = cq & 7;
            const float* arow = s.u.attn + (h * NT + i) * 52;
            const float4* vb = vs4 + (h * NT) * 9 + dq;
            float4 acc = make_float4(0.f, 0.f, 0.f, 0.f);
            #pragma unroll
            for (int j = 0; j < 48; j += 4) {
                float4 a = *(const float4*)(arow + j);
                float4 w0 = vb[(j + 0) * 9];
                float4 w1 = vb[(j + 1) * 9];
                float4 w2 = vb[(j + 2) * 9];
                float4 w3 = vb[(j + 3) * 9];
                acc.x += a.x * w0.x + a.y * w1.x + a.z * w2.x + a.w * w3.x;
                acc.y += a.x * w0.y + a.y * w1.y + a.z * w2.y + a.w * w3.y;
                acc.z += a.x * w0.z + a.y * w1.z + a.z * w2.z + a.w * w3.z;
                acc.w += a.x * w0.w + a.y * w1.w + a.z * w2.w + a.w * w3.w;
            }
            {
                float a48 = arow[48];
                float4 wl = vb[48 * 9];
                acc.x += a48 * wl.x; acc.y += a48 * wl.y;
                acc.z += a48 * wl.z; acc.w += a48 * wl.w;
            }
            os4[i * 33 + cq] = make_float4(to_tf32(acc.x), to_tf32(acc.y),
                                           to_tf32(acc.z), to_tf32(acc.w));
        }
    }
    __syncthreads();

    // ---------------- proj via tf32 mma: (64)x128x128, W in 2 chunks of 64 cols ------
    {
        const float* osf = s.u2.os;
        const float* pwf = s.u.pw;
        for (int pt = 0; pt < 2; pt++) {
            const float4* w4 = (const float4*)(proj_w + (size_t)pt * 64 * DIMC);
            float4* pw4 = (float4*)s.u.pw;
            for (int li = tid; li < 64 * 32; li += THREADS) {
                int r = li >> 5, kq = li & 31;
                float4 v = w4[li];
                pw4[r * 33 + kq] = make_float4(to_tf32(v.x), to_tf32(v.y), to_tf32(v.z), to_tf32(v.w));
            }
            __syncthreads();

            float acc[2][2][4] = {};
            #pragma unroll
            for (int ks = 0; ks < 16; ks++) {
                const int k0 = ks * 8;
                uint32_t A[2][4], B[2][2];
                #pragma unroll
                for (int mt = 0; mt < 2; mt++) {
                    const float* p = osf + (mt2 * 32 + mt * 16 + g) * 132 + k0 + t;
                    A[mt][0] = __float_as_uint(p[0]);
                    A[mt][1] = __float_as_uint(p[8 * 132]);
                    A[mt][2] = __float_as_uint(p[4]);
                    A[mt][3] = __float_as_uint(p[8 * 132 + 4]);
                }
                #pragma unroll
                for (int nt = 0; nt < 2; nt++) {
                    const float* p = pwf + (nq * 16 + nt * 8 + g) * 132 + k0 + t;
                    B[nt][0] = __float_as_uint(p[0]);
                    B[nt][1] = __float_as_uint(p[4]);
                }
                #pragma unroll
                for (int mt = 0; mt < 2; mt++)
                    #pragma unroll
                    for (int nt = 0; nt < 2; nt++)
                        mma_tf32(acc[mt][nt], A[mt], B[nt]);
            }

            float* outb = out + (size_t)b * NT * DIMC;
            #pragma unroll
            for (int mt = 0; mt < 2; mt++) {
                const int r0 = mt2 * 32 + mt * 16 + g;
                #pragma unroll
                for (int nt = 0; nt < 2; nt++) {
                    const int j0 = pt * 64 + nq * 16 + nt * 8 + t * 2;
                    float bj0 = s.bp[j0], bj1 = s.bp[j0 + 1];
                    if (r0 < NT) {
                        outb[r0 * DIMC + j0]     = acc[mt][nt][0] + bj0;
                        outb[r0 * DIMC + j0 + 1] = acc[mt][nt][1] + bj1;
                    }
                    if (r0 + 8 < NT) {
                        outb[(r0 + 8) * DIMC + j0]     = acc[mt][nt][2] + bj0;
                        outb[(r0 + 8) * DIMC + j0 + 1] = acc[mt][nt][3] + bj1;
                    }
                }
            }
            __syncthreads();
        }
    }
}

extern "C" void kernel_launch(void* const* d_in, const int* in_sizes, int n_in,
                              void* d_out, int out_size) {
    const float* x      = (const float*)d_in[0];
    const float* mask   = (const float*)d_in[1];
    const float* qkv_w  = (const float*)d_in[2];
    const float* qkv_b  = (const float*)d_in[3];
    const float* rpb_t  = (const float*)d_in[4];
    const float* proj_w = (const float*)d_in[5];
    const float* proj_b = (const float*)d_in[6];
    const int*   rel    = (const int*)d_in[7];
    float* out = (float*)d_out;

    int B  = in_sizes[0] / (NT * DIMC);     // 4096
    int nW = in_sizes[1] / (NT * NT);       // 64

    size_t smem = sizeof(SMem);
    cudaFuncSetAttribute(wa_kernel, cudaFuncAttributeMaxDynamicSharedMemorySize, (int)smem);
    wa_kernel<<<B, THREADS, smem>>>(x, mask, qkv_w, qkv_b, rpb_t, proj_w, proj_b, rel, out, nW);
}